// round 11
// baseline (speedup 1.0000x reference)
#include <cuda_runtime.h>
#include <math.h>

#define NAT 8192
#define NEg 131072
#define FD 128
#define F3 384
#define NBs 20
#define NHd 64

__device__ __forceinline__ float sigf(float x){ return 1.f/(1.f+expf(-x)); }
__device__ __forceinline__ float siluf(float x){ return x*sigf(x); }
__device__ __forceinline__ float silugf(float z){ float s=sigf(z); return s*(1.f+z*(1.f-s)); }

constexpr float RC  = 5.0f;
constexpr float PIF = 3.14159265358979323846f;

constexpr size_t NF =(size_t)NAT*FD;
constexpr size_t N3F=3*NF;
constexpr size_t NF3=(size_t)NAT*F3;
constexpr size_t N2F=2*NF;
constexpr size_t NHs=(size_t)NAT*NHd;
constexpr size_t E1=NEg, E3=3*(size_t)NEg, ENB=(size_t)NEg*NBs;

// float offsets into g_buf
constexpr size_t O_d    =0;
constexpr size_t O_unit =O_d+E1;
constexpr size_t O_rbf  =O_unit+E3;
constexpr size_t O_fcut =O_rbf+ENB;
constexpr size_t O_x0   =O_fcut+E1;
constexpr size_t O_x1   =O_x0+NF;
constexpr size_t O_x2   =O_x1+NF;
constexpr size_t O_xm0  =O_x2+NF;
constexpr size_t O_xm1  =O_xm0+NF;
constexpr size_t O_v0   =O_xm1+NF;
constexpr size_t O_v1   =O_v0+N3F;
constexpr size_t O_v2   =O_v1+N3F;
constexpr size_t O_vm0  =O_v2+N3F;
constexpr size_t O_vm1  =O_vm0+N3F;
constexpr size_t O_z1   =O_vm1+N3F;        // 2*NF
constexpr size_t O_phi  =O_z1+2*NF;        // 2*NF3
constexpr size_t O_z2   =O_phi+2*NF3;      // 2*NF
constexpr size_t O_a    =O_z2+2*NF;        // 2*NF3
constexpr size_t O_uv   =O_a+2*NF3;        // 2 blocks x [3NAT,256] interleaved uv|vv
constexpr size_t O_vn   =O_uv+4*N3F;       // 2*NF
constexpr size_t O_cat  =O_vn+2*NF;        // N2F (also s1 temp)
constexpr size_t O_z3   =O_cat+N2F;        // NHs
constexpr size_t O_s3   =O_z3+NHs;         // NHs (reused as gz3)
constexpr size_t O_gxA  =O_s3+NHs;
constexpr size_t O_gxB  =O_gxA+NF;
constexpr size_t O_gv0  =O_gxB+NF;
constexpr size_t O_gv1  =O_gv0+N3F;
constexpr size_t O_gv2  =O_gv1+N3F;
constexpr size_t O_ga   =O_gv2+N3F;        // NF3
constexpr size_t O_guv  =O_ga+NF3;         // [3NAT,256] interleaved guv|gvv scratch
constexpr size_t O_gs   =O_guv+2*N3F;      // NF
constexpr size_t O_gcat =O_gs+NF;          // N2F
constexpr size_t O_gphi =O_gcat+N2F;       // NF3
constexpr size_t O_ggd  =O_gphi+NF3;       // E1  accumulated gd
constexpr size_t O_ggfc =O_ggd+E1;         // E1  accumulated gfcut
constexpr size_t O_ggu  =O_ggfc+E1;        // E3  accumulated gunit
constexpr size_t O_gr   =O_ggu+E3;         // E3  per-edge coord grad
constexpr size_t O_drbf =O_gr+E3;          // ENB d(rbf)/dd table
constexpr size_t O_wcat =O_drbf+ENB;       // 2 x 128*256 combined [U|V]
constexpr size_t TOTALF =O_wcat+2*128*256;

__device__ float  g_buf[TOTALF];
__device__ double g_epart[1024];
// CSR: roles [0,NAT)=dst lists, [NAT,2*NAT)=src lists
__device__ int g_cnt[2*NAT];
__device__ int g_cur[2*NAT];
__device__ int g_off[2*NAT+1];
__device__ int g_lst[2*NEg];

// ----------------------------------------------------------------------------
__global__ void zero_f_k(float* p, size_t n){
    size_t i=(size_t)blockIdx.x*blockDim.x+threadIdx.x;
    size_t stride=(size_t)gridDim.x*blockDim.x;
    for(; i<n; i+=stride) p[i]=0.f;
}
__global__ void zero_ii_k(){
    int i=blockIdx.x*blockDim.x+threadIdx.x;
    if(i<2*NAT){ g_cnt[i]=0; g_cur[i]=0; }
}
__global__ void wcat_k(const float* __restrict__ U, const float* __restrict__ V){
    int i=blockIdx.x*blockDim.x+threadIdx.x;
    if(i>=2*128*256) return;
    int b=i>>15, rem=i&32767;
    int k=rem>>8, j=rem&255;
    float v=(j<128)? U[(size_t)b*16384+k*128+j] : V[(size_t)b*16384+k*128+j-128];
    g_buf[O_wcat+i]=v;
}

// ----------------------------------------------------------------------------
__global__ void edge_geom_k(const float* __restrict__ coord, const int* __restrict__ ei){
    int e=blockIdx.x*blockDim.x+threadIdx.x;
    if(e>=NEg) return;
    int src=ei[e], dst=ei[NEg+e];
    float rx=coord[dst*3+0]-coord[src*3+0];
    float ry=coord[dst*3+1]-coord[src*3+1];
    float rz=coord[dst*3+2]-coord[src*3+2];
    float d=sqrtf(rx*rx+ry*ry+rz*rz+1e-12f);
    float inv=1.f/d;
    g_buf[O_d+e]=d;
    g_buf[O_unit+(size_t)e*3+0]=rx*inv;
    g_buf[O_unit+(size_t)e*3+1]=ry*inv;
    g_buf[O_unit+(size_t)e*3+2]=rz*inv;
    const float C=sqrtf(2.f/RC);
    #pragma unroll
    for(int k=0;k<NBs;k++){
        float a=(k+1)*PIF/RC;
        float s,c; sincosf(a*d,&s,&c);
        g_buf[O_rbf +(size_t)e*NBs+k]=C*s*inv;
        g_buf[O_drbf+(size_t)e*NBs+k]=C*(a*c - s*inv)*inv;
    }
    g_buf[O_fcut+e]=(d<RC)?0.5f*(cosf(PIF*d/RC)+1.f):0.f;
}

__global__ void embed_k(const int* __restrict__ at_no, const float* __restrict__ emb){
    size_t i=(size_t)blockIdx.x*blockDim.x+threadIdx.x;
    if(i>=NF) return;
    int n=(int)(i>>7), f=(int)(i&127);
    g_buf[O_x0+i]=emb[(size_t)at_no[n]*FD+f];
}

// ----------------------------------------------------------------------------
// fp32 GEMM: C[M,N]=act(A[M,K]@Wop+bias+Cadd). BM=BN=64, BK=16, 256 threads,
// 4x4 microtile, float4, double-buffered. M%64==0,N%64==0,K%16==0.
template<int TRANSW>
__global__ __launch_bounds__(256) void gemm3_k(
    const float* __restrict__ A, const float* __restrict__ W,
    const float* __restrict__ bias, const float* __restrict__ Cadd,
    float* __restrict__ C, float* __restrict__ Z,
    int M,int K,int N,int act)
{
    __shared__ float As[2][16][68];
    __shared__ float Ws[2][16][68];
    const int tid=threadIdx.x;
    const int tx=tid&15, ty=tid>>4;
    const int m0=blockIdx.y*64, n0=blockIdx.x*64;

    float acc[4][4];
    #pragma unroll
    for(int i=0;i<4;i++)
        #pragma unroll
        for(int j=0;j<4;j++) acc[i][j]=0.f;

    const int nt=K>>4;
    float4 pa, pw;

    {
        int r=tid>>2, kq=tid&3;
        pa=*(const float4*)&A[(size_t)(m0+r)*K + kq*4];
        if(TRANSW){
            pw=*(const float4*)&W[(size_t)(n0+r)*K + kq*4];
        } else {
            int kk=tid>>4, nq=tid&15;
            pw=*(const float4*)&W[(size_t)kk*N + n0+nq*4];
        }
    }
    {
        int r=tid>>2, kq=tid&3;
        As[0][kq*4+0][r]=pa.x; As[0][kq*4+1][r]=pa.y;
        As[0][kq*4+2][r]=pa.z; As[0][kq*4+3][r]=pa.w;
        if(TRANSW){
            Ws[0][kq*4+0][r]=pw.x; Ws[0][kq*4+1][r]=pw.y;
            Ws[0][kq*4+2][r]=pw.z; Ws[0][kq*4+3][r]=pw.w;
        } else {
            int kk=tid>>4, nq=tid&15;
            *(float4*)&Ws[0][kk][nq*4]=pw;
        }
    }
    __syncthreads();

    for(int t=0;t<nt;t++){
        int buf=t&1;
        if(t+1<nt){
            int k0=(t+1)*16;
            int r=tid>>2, kq=tid&3;
            pa=*(const float4*)&A[(size_t)(m0+r)*K + k0 + kq*4];
            if(TRANSW){
                pw=*(const float4*)&W[(size_t)(n0+r)*K + k0 + kq*4];
            } else {
                int kk=tid>>4, nq=tid&15;
                pw=*(const float4*)&W[(size_t)(k0+kk)*N + n0+nq*4];
            }
        }
        #pragma unroll
        for(int kk=0;kk<16;kk++){
            float4 a0=*(const float4*)&As[buf][kk][ty*4];
            float4 w0=*(const float4*)&Ws[buf][kk][tx*4];
            float av[4]={a0.x,a0.y,a0.z,a0.w};
            #pragma unroll
            for(int i=0;i<4;i++){
                acc[i][0]+=av[i]*w0.x;
                acc[i][1]+=av[i]*w0.y;
                acc[i][2]+=av[i]*w0.z;
                acc[i][3]+=av[i]*w0.w;
            }
        }
        if(t+1<nt){
            int nb=buf^1;
            int r=tid>>2, kq=tid&3;
            As[nb][kq*4+0][r]=pa.x; As[nb][kq*4+1][r]=pa.y;
            As[nb][kq*4+2][r]=pa.z; As[nb][kq*4+3][r]=pa.w;
            if(TRANSW){
                Ws[nb][kq*4+0][r]=pw.x; Ws[nb][kq*4+1][r]=pw.y;
                Ws[nb][kq*4+2][r]=pw.z; Ws[nb][kq*4+3][r]=pw.w;
            } else {
                int kk=tid>>4, nq=tid&15;
                *(float4*)&Ws[nb][kk][nq*4]=pw;
            }
            __syncthreads();
        }
    }

    const int n=n0+tx*4;
    float4 bb={0.f,0.f,0.f,0.f};
    if(bias) bb=*(const float4*)&bias[n];
    #pragma unroll
    for(int i=0;i<4;i++){
        int m=m0+ty*4+i;
        float4 v={acc[i][0]+bb.x,acc[i][1]+bb.y,acc[i][2]+bb.z,acc[i][3]+bb.w};
        size_t off=(size_t)m*N+n;
        if(Cadd){
            float4 cc=*(const float4*)&Cadd[off];
            v.x+=cc.x; v.y+=cc.y; v.z+=cc.z; v.w+=cc.w;
        }
        if(act==1){
            if(Z) *(float4*)&Z[off]=v;
            v.x=siluf(v.x); v.y=siluf(v.y); v.z=siluf(v.z); v.w=siluf(v.w);
        } else if(act==2){
            float4 zz=*(const float4*)&Z[off];
            v.x*=silugf(zz.x); v.y*=silugf(zz.y); v.z*=silugf(zz.z); v.w*=silugf(zz.w);
        }
        *(float4*)&C[off]=v;
    }
}

static inline void gemm2(const float*A,const float*W,const float*b,const float*Cadd,
                         float*C,float*Z,int M,int K,int N,int act,int transW){
    dim3 g(N/64, M/64);
    if(transW) gemm3_k<1><<<g,256>>>(A,W,b,Cadd,C,Z,M,K,N,act);
    else       gemm3_k<0><<<g,256>>>(A,W,b,Cadd,C,Z,M,K,N,act);
}

// ----------------------------------------------------------------------------
// CSR build
__global__ void count_k(const int* __restrict__ ei){
    int e=blockIdx.x*blockDim.x+threadIdx.x;
    if(e>=NEg) return;
    atomicAdd(&g_cnt[ei[NEg+e]],1);
    atomicAdd(&g_cnt[NAT+ei[e]],1);
}
__global__ __launch_bounds__(1024) void scan_k(){
    __shared__ int part[1024];
    int t=threadIdx.x;
    int loc[16]; int s=0;
    #pragma unroll
    for(int i=0;i<16;i++){ loc[i]=s; s+=g_cnt[t*16+i]; }
    part[t]=s;
    __syncthreads();
    if(t==0){
        int acc=0;
        for(int i=0;i<1024;i++){ int v=part[i]; part[i]=acc; acc+=v; }
        g_off[2*NAT]=acc;
    }
    __syncthreads();
    int b=part[t];
    #pragma unroll
    for(int i=0;i<16;i++) g_off[t*16+i]=b+loc[i];
}
__global__ void fill_k(const int* __restrict__ ei){
    int e=blockIdx.x*blockDim.x+threadIdx.x;
    if(e>=NEg) return;
    int d=ei[NEg+e], s=ei[e];
    int p=atomicAdd(&g_cur[d],1);      g_lst[g_off[d]+p]=e;
    int q=atomicAdd(&g_cur[NAT+s],1);  g_lst[g_off[NAT+s]+q]=e;
}
__global__ void sort_k(){
    int l=blockIdx.x*blockDim.x+threadIdx.x;
    if(l>=2*NAT) return;
    int s=g_off[l], en=g_off[l+1];
    for(int i=s+1;i<en;i++){
        int v=g_lst[i]; int j=i-1;
        while(j>=s && g_lst[j]>v){ g_lst[j+1]=g_lst[j]; j--; }
        g_lst[j+1]=v;
    }
}

// ----------------------------------------------------------------------------
// message forward: one block per DST atom, register accumulation, no atomics
__global__ __launch_bounds__(128) void msg_fwd_csr_k(
    const int* __restrict__ ei, const float* __restrict__ Wr, const float* __restrict__ br,
    const float* __restrict__ phi, const float* __restrict__ x_in,
    const float* __restrict__ v_in,
    float* __restrict__ xmid, float* __restrict__ vmid)
{
    __shared__ float wS[NBs*F3];
    __shared__ float brS[F3];
    int t=threadIdx.x;
    for(int i=t;i<NBs*F3/4;i+=128) ((float4*)wS)[i]=((const float4*)Wr)[i];
    if(t<F3/4) ((float4*)brS)[t]=((const float4*)br)[t];
    __syncthreads();
    int n=blockIdx.x;
    int c0=t,c1=FD+t,c2=2*FD+t;
    float b0=brS[c0],b1=brS[c1],b2=brS[c2];
    float ax =x_in[(size_t)n*FD+t];
    float av0=v_in[((size_t)n*3+0)*FD+t];
    float av1=v_in[((size_t)n*3+1)*FD+t];
    float av2=v_in[((size_t)n*3+2)*FD+t];
    int s0=g_off[n], s1=g_off[n+1];
    for(int j=s0;j<s1;j++){
        int e=g_lst[j];
        int src=ei[e];
        float fc=g_buf[O_fcut+e];
        float u0=g_buf[O_unit+(size_t)e*3+0];
        float u1=g_buf[O_unit+(size_t)e*3+1];
        float u2=g_buf[O_unit+(size_t)e*3+2];
        const float* rb=&g_buf[O_rbf+(size_t)e*NBs];
        float g0=b0,g1=b1,g2=b2;
        #pragma unroll
        for(int k=0;k<NBs;k++){
            float r=rb[k];
            g0+=r*wS[k*F3+c0]; g1+=r*wS[k*F3+c1]; g2+=r*wS[k*F3+c2];
        }
        float f0=g0*fc, f1=g1*fc, f2=g2*fc;
        const float* ps=phi+(size_t)src*F3;
        ax += ps[c0]*f0;
        float m1=ps[c1]*f1, m2=ps[c2]*f2;
        av0 += m1*v_in[((size_t)src*3+0)*FD+t]+m2*u0;
        av1 += m1*v_in[((size_t)src*3+1)*FD+t]+m2*u1;
        av2 += m1*v_in[((size_t)src*3+2)*FD+t]+m2*u2;
    }
    xmid[(size_t)n*FD+t]=ax;
    vmid[((size_t)n*3+0)*FD+t]=av0;
    vmid[((size_t)n*3+1)*FD+t]=av1;
    vmid[((size_t)n*3+2)*FD+t]=av2;
}

// message backward: one block per SRC atom, register accumulation
__global__ __launch_bounds__(128) void msg_bwd_csr_k(
    const int* __restrict__ ei, const float* __restrict__ Wr, const float* __restrict__ br,
    const float* __restrict__ phi, const float* __restrict__ v_in,
    const float* __restrict__ gx_mid, const float* __restrict__ gv_mid,
    float* __restrict__ gv_prev, float* __restrict__ gphi)
{
    __shared__ float wS[NBs*F3];
    __shared__ float brS[F3];
    __shared__ float accS[8];
    int t=threadIdx.x;
    for(int i=t;i<NBs*F3/4;i+=128) ((float4*)wS)[i]=((const float4*)Wr)[i];
    if(t<F3/4) ((float4*)brS)[t]=((const float4*)br)[t];
    __syncthreads();
    int m=blockIdx.x;
    int c0=t,c1=FD+t,c2=2*FD+t;
    int lane=t&31;
    float b0=brS[c0],b1=brS[c1],b2=brS[c2];
    float p0=phi[(size_t)m*F3+c0];
    float p1=phi[(size_t)m*F3+c1];
    float p2=phi[(size_t)m*F3+c2];
    float vs0=v_in[((size_t)m*3+0)*FD+t];
    float vs1=v_in[((size_t)m*3+1)*FD+t];
    float vs2=v_in[((size_t)m*3+2)*FD+t];
    float agv0=gv_mid[((size_t)m*3+0)*FD+t];
    float agv1=gv_mid[((size_t)m*3+1)*FD+t];
    float agv2=gv_mid[((size_t)m*3+2)*FD+t];
    float aph0=0.f, aph1=0.f, aph2=0.f;
    int s0=g_off[NAT+m], s1=g_off[NAT+m+1];
    for(int j=s0;j<s1;j++){
        int e=g_lst[j];
        if(t<5) accS[t]=0.f;
        int dst=ei[NEg+e];
        float fc=g_buf[O_fcut+e];
        float u0=g_buf[O_unit+(size_t)e*3+0];
        float u1=g_buf[O_unit+(size_t)e*3+1];
        float u2=g_buf[O_unit+(size_t)e*3+2];
        const float* rb=&g_buf[O_rbf +(size_t)e*NBs];
        const float* db=&g_buf[O_drbf+(size_t)e*NBs];
        float g0=b0,g1=b1,g2=b2;
        float wd0=0.f,wd1=0.f,wd2=0.f;
        #pragma unroll
        for(int k=0;k<NBs;k++){
            float w0=wS[k*F3+c0], w1=wS[k*F3+c1], w2=wS[k*F3+c2];
            float r=rb[k], dr=db[k];
            g0+=r*w0; g1+=r*w1; g2+=r*w2;
            wd0+=dr*w0; wd1+=dr*w1; wd2+=dr*w2;
        }
        float f0=g0*fc,f1=g1*fc,f2=g2*fc;
        float gds=gx_mid[(size_t)dst*FD+t];
        float gd0=gv_mid[((size_t)dst*3+0)*FD+t];
        float gd1=gv_mid[((size_t)dst*3+1)*FD+t];
        float gd2=gv_mid[((size_t)dst*3+2)*FD+t];
        float gm1=gd0*vs0+gd1*vs1+gd2*vs2;
        float gm2=gd0*u0+gd1*u1+gd2*u2;
        float m1=p1*f1, m2=p2*f2;
        agv0+=m1*gd0; agv1+=m1*gd1; agv2+=m1*gd2;
        aph0+=gds*f0; aph1+=gm1*f1; aph2+=gm2*f2;
        float gf0=gds*p0, gf1=gm1*p1, gf2=gm2*p2;
        float gg0=gf0*fc, gg1=gf1*fc, gg2=gf2*fc;
        float vals[5];
        vals[0]=gg0*wd0+gg1*wd1+gg2*wd2;
        vals[1]=gf0*g0+gf1*g1+gf2*g2;
        vals[2]=gd0*m2; vals[3]=gd1*m2; vals[4]=gd2*m2;
        __syncthreads();
        #pragma unroll
        for(int q=0;q<5;q++){
            float v=vals[q];
            #pragma unroll
            for(int o=16;o;o>>=1) v+=__shfl_down_sync(0xffffffffu,v,o);
            if(lane==0) atomicAdd(&accS[q],v);
        }
        __syncthreads();
        if(t==0)      g_buf[O_ggd +e]+=accS[0];
        else if(t==1) g_buf[O_ggfc+e]+=accS[1];
        else if(t<5)  g_buf[O_ggu+(size_t)e*3+(t-2)]+=accS[t];
    }
    gv_prev[((size_t)m*3+0)*FD+t]=agv0;
    gv_prev[((size_t)m*3+1)*FD+t]=agv1;
    gv_prev[((size_t)m*3+2)*FD+t]=agv2;
    gphi[(size_t)m*F3+c0]=aph0;
    gphi[(size_t)m*F3+c1]=aph1;
    gphi[(size_t)m*F3+c2]=aph2;
}

// ----------------------------------------------------------------------------
// uvv layout: [3*NAT, 256], cols 0-127 = uv, 128-255 = vv
__global__ void vnorm_cat_k(const float* __restrict__ uvv, const float* __restrict__ xmid,
                            float* __restrict__ vn, float* __restrict__ cat){
    size_t i=(size_t)blockIdx.x*blockDim.x+threadIdx.x;
    if(i>=NF) return;
    int n=(int)(i>>7), f=(int)(i&127);
    float a=uvv[((size_t)n*3+0)*256+128+f];
    float b=uvv[((size_t)n*3+1)*256+128+f];
    float c=uvv[((size_t)n*3+2)*256+128+f];
    float v=sqrtf(a*a+b*b+c*c+1e-12f);
    vn[i]=v;
    cat[(size_t)n*2*FD+f]=xmid[i];
    cat[(size_t)n*2*FD+FD+f]=v;
}

__global__ void upd_fwd_k(const float* __restrict__ a, const float* __restrict__ uvv,
                          const float* __restrict__ vmid, const float* __restrict__ xmid,
                          float* __restrict__ xout, float* __restrict__ vout){
    size_t i=(size_t)blockIdx.x*blockDim.x+threadIdx.x;
    if(i>=NF) return;
    int n=(int)(i>>7), f=(int)(i&127);
    const float* an=a+(size_t)n*F3;
    float avv=an[f], asv=an[FD+f], ass=an[2*FD+f];
    float sdot=0.f;
    #pragma unroll
    for(int k=0;k<3;k++){
        size_t r2=((size_t)n*3+k)*256+f;
        float u=uvv[r2], w=uvv[r2+128];
        sdot+=u*w;
        vout[((size_t)n*3+k)*FD+f]=vmid[((size_t)n*3+k)*FD+f]+avv*u;
    }
    xout[i]=xmid[i]+asv*sdot+ass;
}

__global__ void energy_k(const float* __restrict__ s3, const float* __restrict__ ow2,
                         const float* __restrict__ ob2, const float* __restrict__ atom_sp,
                         const int* __restrict__ at_no){
    __shared__ double wsum[8];
    int warp=threadIdx.x>>5, lane=threadIdx.x&31;
    int n=blockIdx.x*8+warp;
    float val=s3[(size_t)n*NHd+lane]*ow2[lane]+s3[(size_t)n*NHd+32+lane]*ow2[32+lane];
    #pragma unroll
    for(int o=16;o;o>>=1) val+=__shfl_down_sync(0xffffffffu,val,o);
    if(lane==0) wsum[warp]=(double)val+(double)ob2[0]+(double)atom_sp[at_no[n]];
    __syncthreads();
    if(threadIdx.x==0){
        double s=0.0;
        #pragma unroll
        for(int i=0;i<8;i++) s+=wsum[i];
        g_epart[blockIdx.x]=s;
    }
}
__global__ void store_e_k(float* out){
    __shared__ double sh[256];
    int t=threadIdx.x;
    sh[t]=g_epart[t]+g_epart[t+256]+g_epart[t+512]+g_epart[t+768];
    __syncthreads();
    for(int o=128;o;o>>=1){ if(t<o) sh[t]+=sh[t+o]; __syncthreads(); }
    if(t==0) out[0]=(float)sh[0];
}

__global__ void gz3_k(const float* __restrict__ z3, const float* __restrict__ ow2,
                      float* __restrict__ gz3){
    size_t i=(size_t)blockIdx.x*blockDim.x+threadIdx.x;
    if(i>=NHs) return;
    int h=(int)(i&(NHd-1));
    gz3[i]=ow2[h]*silugf(z3[i]);
}

// update backward part 1: reads uvv, writes ga + guvv (interleaved [.,256])
__global__ void upd_bwd1_k(const float* __restrict__ gx_in, const float* __restrict__ gv_in,
                           const float* __restrict__ uvv, const float* __restrict__ a,
                           float* __restrict__ ga, float* __restrict__ guvv){
    size_t i=(size_t)blockIdx.x*blockDim.x+threadIdx.x;
    if(i>=NF) return;
    int n=(int)(i>>7), f=(int)(i&127);
    const float* an=a+(size_t)n*F3;
    float avv=an[f], asv=an[FD+f];
    float gx=gx_in[i];
    float sdot=0.f, gavv=0.f;
    float uvr[3],vvr[3],gvr[3];
    #pragma unroll
    for(int k=0;k<3;k++){
        size_t r2=((size_t)n*3+k)*256+f;
        uvr[k]=uvv[r2]; vvr[k]=uvv[r2+128];
        gvr[k]=gv_in[((size_t)n*3+k)*FD+f];
        sdot+=uvr[k]*vvr[k];
        gavv+=gvr[k]*uvr[k];
    }
    float gsdot=gx*asv;
    float* gan=ga+(size_t)n*F3;
    gan[f]=gavv; gan[FD+f]=gx*sdot; gan[2*FD+f]=gx;
    #pragma unroll
    for(int k=0;k<3;k++){
        size_t r2=((size_t)n*3+k)*256+f;
        guvv[r2]=gvr[k]*avv+gsdot*vvr[k];
        guvv[r2+128]=gsdot*uvr[k];
    }
}

// update backward part 3: gvv part of guvv += (gvn/vn)*vv
__global__ void upd_bwd3_k(const float* __restrict__ gcat, const float* __restrict__ gx_in,
                           const float* __restrict__ uvv, const float* __restrict__ vn,
                           float* __restrict__ gx_mid, float* __restrict__ guvv){
    size_t i=(size_t)blockIdx.x*blockDim.x+threadIdx.x;
    if(i>=NF) return;
    int n=(int)(i>>7), f=(int)(i&127);
    gx_mid[i]=gx_in[i]+gcat[(size_t)n*2*FD+f];
    float gvn=gcat[(size_t)n*2*FD+FD+f];
    float inv=gvn/vn[i];
    #pragma unroll
    for(int k=0;k<3;k++){
        size_t r2=((size_t)n*3+k)*256+f;
        guvv[r2+128]+=inv*uvv[r2+128];
    }
}

// final per-edge coord gradient
__global__ void edge_gr_k(){
    int e=blockIdx.x*blockDim.x+threadIdx.x;
    if(e>=NEg) return;
    float d=g_buf[O_d+e];
    float inv=1.f/d;
    float u0=g_buf[O_unit+(size_t)e*3+0];
    float u1=g_buf[O_unit+(size_t)e*3+1];
    float u2=g_buf[O_unit+(size_t)e*3+2];
    float gd=g_buf[O_ggd+e];
    if(d<RC) gd+=g_buf[O_ggfc+e]*(-0.5f*PIF/RC*sinf(PIF*d/RC));
    float gu0=g_buf[O_ggu+(size_t)e*3+0];
    float gu1=g_buf[O_ggu+(size_t)e*3+1];
    float gu2=g_buf[O_ggu+(size_t)e*3+2];
    float dot=gu0*u0+gu1*u1+gu2*u2;
    g_buf[O_gr+(size_t)e*3+0]=gd*u0+(gu0-dot*u0)*inv;
    g_buf[O_gr+(size_t)e*3+1]=gd*u1+(gu1-dot*u1)*inv;
    g_buf[O_gr+(size_t)e*3+2]=gd*u2+(gu2-dot*u2)*inv;
}

// deterministic reference-order scatter
__global__ void out_k(float* __restrict__ gout){
    int i=blockIdx.x*blockDim.x+threadIdx.x;
    if(i>=NAT*3) return;
    int n=i/3, c=i%3;
    float A=0.f;
    int s0=g_off[n], e0=g_off[n+1];
    for(int j=s0;j<e0;j++){ int e=g_lst[j]; A+=g_buf[O_gr+(size_t)e*3+c]; }
    float Bv=0.f;
    int s1=g_off[NAT+n], e1=g_off[NAT+n+1];
    for(int j=s1;j<e1;j++){ int e=g_lst[j]; Bv-=g_buf[O_gr+(size_t)e*3+c]; }
    gout[i]=A+Bv;
}

// ----------------------------------------------------------------------------
extern "C" void kernel_launch(void* const* d_in, const int* in_sizes, int n_in,
                              void* d_out, int out_size){
    float* B=nullptr;
    cudaGetSymbolAddress((void**)&B, g_buf);

    const int*   at_no=(const int*)d_in[0];
    const float* coord=(const float*)d_in[1];
    const int*   ei   =(const int*)d_in[2];
    int p=(in_sizes[3]==1)?5:3;
    const float* emb    =(const float*)d_in[p+0];
    const float* atom_sp=(const float*)d_in[p+1];
    const float* msg_w1 =(const float*)d_in[p+2];
    const float* msg_b1 =(const float*)d_in[p+3];
    const float* msg_w2 =(const float*)d_in[p+4];
    const float* msg_b2 =(const float*)d_in[p+5];
    const float* msg_wr =(const float*)d_in[p+6];
    const float* msg_br =(const float*)d_in[p+7];
    const float* upd_u  =(const float*)d_in[p+8];
    const float* upd_v  =(const float*)d_in[p+9];
    const float* upd_w1 =(const float*)d_in[p+10];
    const float* upd_b1 =(const float*)d_in[p+11];
    const float* upd_w2 =(const float*)d_in[p+12];
    const float* upd_b2 =(const float*)d_in[p+13];
    const float* out_w1 =(const float*)d_in[p+14];
    const float* out_b1 =(const float*)d_in[p+15];
    const float* out_w2 =(const float*)d_in[p+16];
    const float* out_b2 =(const float*)d_in[p+17];
    float* out=(float*)d_out;

    const size_t xs[3]={O_x0,O_x1,O_x2};
    const size_t vs[3]={O_v0,O_v1,O_v2};

    // prologue (first GEMM early for ncu window)
    edge_geom_k<<<(NEg+255)/256,256>>>(coord,ei);             // 0
    embed_k<<<(int)((NF+255)/256),256>>>(at_no,emb);          // 1
    zero_f_k<<<4096,256>>>(B+O_v0,N3F);                       // 2
    gemm2(B+O_x0, msg_w1, msg_b1, nullptr, B+O_cat,
          B+O_z1, NAT,FD,FD,1,0);                             // 3 <- target profile
    gemm2(B+O_cat, msg_w2, msg_b2, nullptr, B+O_phi,
          nullptr, NAT,FD,F3,0,0);                            // 4
    zero_ii_k<<<64,256>>>();
    wcat_k<<<(2*128*256+255)/256,256>>>(upd_u, upd_v);
    count_k<<<(NEg+255)/256,256>>>(ei);
    scan_k<<<1,1024>>>();
    fill_k<<<(NEg+255)/256,256>>>(ei);
    sort_k<<<(2*NAT+255)/256,256>>>();

    // ---- forward ----
    for(int b=0;b<2;b++){
        float* x_in=B+xs[b];  float* v_in=B+vs[b];
        float* xmid=B+(b?O_xm1:O_xm0);
        float* vmid=B+(b?O_vm1:O_vm0);
        float* uvv =B+O_uv+(size_t)b*2*N3F;
        if(b==1){
            gemm2(x_in, msg_w1+(size_t)b*FD*FD, msg_b1+(size_t)b*FD,
                  nullptr, B+O_cat, B+O_z1+(size_t)b*NF, NAT,FD,FD,1,0);
            gemm2(B+O_cat, msg_w2+(size_t)b*FD*F3, msg_b2+(size_t)b*F3,
                  nullptr, B+O_phi+(size_t)b*NF3, nullptr, NAT,FD,F3,0,0);
        }
        msg_fwd_csr_k<<<NAT,128>>>(ei, msg_wr+(size_t)b*NBs*F3, msg_br+(size_t)b*F3,
                                   B+O_phi+(size_t)b*NF3, x_in, v_in, xmid, vmid);
        // uvv = vmid @ [U|V]
        gemm2(vmid, B+O_wcat+(size_t)b*32768, nullptr,nullptr,
              uvv, nullptr, 3*NAT,FD,256,0,0);
        vnorm_cat_k<<<(int)((NF+255)/256),256>>>(uvv, xmid,
                                                 B+O_vn+(size_t)b*NF, B+O_cat);
        gemm2(B+O_cat, upd_w1+(size_t)b*2*FD*FD, upd_b1+(size_t)b*FD,
              nullptr, B+O_gs, B+O_z2+(size_t)b*NF, NAT,2*FD,FD,1,0);
        gemm2(B+O_gs, upd_w2+(size_t)b*FD*F3, upd_b2+(size_t)b*F3,
              nullptr, B+O_a+(size_t)b*NF3, nullptr, NAT,FD,F3,0,0);
        upd_fwd_k<<<(int)((NF+255)/256),256>>>(B+O_a+(size_t)b*NF3, uvv,
                                               vmid, xmid, B+xs[b+1], B+vs[b+1]);
    }

    // ---- readout + energy ----
    gemm2(B+O_x2, out_w1, out_b1, nullptr, B+O_s3, B+O_z3, NAT,FD,NHd,1,0);
    energy_k<<<NAT/8,256>>>(B+O_s3, out_w2, out_b2, atom_sp, at_no);

    // ---- zero geometry-grad accumulators ----
    zero_f_k<<<1024,256>>>(B+O_ggd, 5*E1);

    // ---- backward readout ----
    gz3_k<<<(int)((NHs+255)/256),256>>>(B+O_z3, out_w2, B+O_s3);
    gemm2(B+O_s3, out_w1, nullptr, nullptr, B+O_gxA, nullptr, NAT,NHd,FD,0,1);
    float* gvbuf[3]={B+O_gv0,B+O_gv1,B+O_gv2};
    int ib=0;
    zero_f_k<<<4096,256>>>(gvbuf[0],N3F);

    // ---- backward blocks ----
    for(int b=1;b>=0;b--){
        float* gv_in  =gvbuf[ib];
        float* gv_mid =gvbuf[(ib+1)%3];
        float* gv_prev=gvbuf[(ib+2)%3];
        float* gx_in=B+O_gxA;
        float* gx_mid=B+O_gxB;
        float* v_in=B+vs[b];
        float* uvv =B+O_uv+(size_t)b*2*N3F;

        upd_bwd1_k<<<(int)((NF+255)/256),256>>>(gx_in, gv_in,
                uvv, B+O_a+(size_t)b*NF3, B+O_ga, B+O_guv);
        gemm2(B+O_ga, upd_w2+(size_t)b*FD*F3, nullptr, nullptr,
              B+O_gs, B+O_z2+(size_t)b*NF, NAT,F3,FD,2,1);
        gemm2(B+O_gs, upd_w1+(size_t)b*2*FD*FD, nullptr, nullptr,
              B+O_gcat, nullptr, NAT,FD,2*FD,0,1);
        upd_bwd3_k<<<(int)((NF+255)/256),256>>>(B+O_gcat, gx_in,
                uvv, B+O_vn+(size_t)b*NF, gx_mid, B+O_guv);
        // gv_mid = [guv|gvv] @ [U;V]^T + gv_in   (single K=256 GEMM)
        gemm2(B+O_guv, B+O_wcat+(size_t)b*32768, nullptr, gv_in,
              gv_mid, nullptr, 3*NAT,256,FD,0,1);
        msg_bwd_csr_k<<<NAT,128>>>(ei, msg_wr+(size_t)b*NBs*F3, msg_br+(size_t)b*F3,
                                   B+O_phi+(size_t)b*NF3, v_in, gx_mid, gv_mid,
                                   gv_prev, B+O_gphi);
        if(b>0){
            gemm2(B+O_gphi, msg_w2+(size_t)b*FD*F3, nullptr, nullptr,
                  B+O_gs, B+O_z1+(size_t)b*NF, NAT,F3,FD,2,1);
            gemm2(B+O_gs, msg_w1+(size_t)b*FD*FD, nullptr, gx_mid,
                  B+O_gxA, nullptr, NAT,FD,FD,0,1);
        }
        ib=(ib+2)%3;
    }

    // ---- geometry grads -> coord grads ----
    edge_gr_k<<<(NEg+255)/256,256>>>();
    out_k<<<(3*NAT+255)/256,256>>>(out+1);
    store_e_k<<<1,256>>>(out);
}

// round 12
// speedup vs baseline: 1.5129x; 1.5129x over previous
#include <cuda_runtime.h>
#include <math.h>

#define NAT 8192
#define NEg 131072
#define FD 128
#define F3 384
#define NBs 20
#define NHd 64

__device__ __forceinline__ float sigf(float x){ return 1.f/(1.f+expf(-x)); }
__device__ __forceinline__ float siluf(float x){ return x*sigf(x); }
__device__ __forceinline__ float silugf(float z){ float s=sigf(z); return s*(1.f+z*(1.f-s)); }

constexpr float RC  = 5.0f;
constexpr float PIF = 3.14159265358979323846f;

constexpr size_t NF =(size_t)NAT*FD;
constexpr size_t N3F=3*NF;
constexpr size_t NF3=(size_t)NAT*F3;
constexpr size_t N2F=2*NF;
constexpr size_t NHs=(size_t)NAT*NHd;
constexpr size_t E1=NEg, E3=3*(size_t)NEg, ENB=(size_t)NEg*NBs;

// float offsets into g_buf
constexpr size_t O_d    =0;
constexpr size_t O_unit =O_d+E1;
constexpr size_t O_rbf  =O_unit+E3;
constexpr size_t O_fcut =O_rbf+ENB;
constexpr size_t O_x0   =O_fcut+E1;
constexpr size_t O_x1   =O_x0+NF;
constexpr size_t O_x2   =O_x1+NF;
constexpr size_t O_xm0  =O_x2+NF;
constexpr size_t O_xm1  =O_xm0+NF;
constexpr size_t O_v0   =O_xm1+NF;
constexpr size_t O_v1   =O_v0+N3F;
constexpr size_t O_v2   =O_v1+N3F;
constexpr size_t O_vm0  =O_v2+N3F;
constexpr size_t O_vm1  =O_vm0+N3F;
constexpr size_t O_z1   =O_vm1+N3F;        // 2*NF
constexpr size_t O_phi  =O_z1+2*NF;        // 2*NF3
constexpr size_t O_z2   =O_phi+2*NF3;      // 2*NF
constexpr size_t O_a    =O_z2+2*NF;        // 2*NF3
constexpr size_t O_uv   =O_a+2*NF3;        // 2 blocks x [3NAT,256] interleaved uv|vv
constexpr size_t O_vn   =O_uv+4*N3F;       // 2*NF
constexpr size_t O_cat  =O_vn+2*NF;        // N2F (also s1 temp)
constexpr size_t O_z3   =O_cat+N2F;        // NHs
constexpr size_t O_s3   =O_z3+NHs;         // NHs (reused as gz3)
constexpr size_t O_gxA  =O_s3+NHs;
constexpr size_t O_gxB  =O_gxA+NF;
constexpr size_t O_gv0  =O_gxB+NF;
constexpr size_t O_gv1  =O_gv0+N3F;
constexpr size_t O_gv2  =O_gv1+N3F;
constexpr size_t O_ga   =O_gv2+N3F;        // NF3
constexpr size_t O_guv  =O_ga+NF3;         // [3NAT,256] interleaved guv|gvv scratch
constexpr size_t O_gs   =O_guv+2*N3F;      // NF
constexpr size_t O_gcat =O_gs+NF;          // N2F
constexpr size_t O_gphi =O_gcat+N2F;       // NF3
constexpr size_t O_ggd  =O_gphi+NF3;       // E1  accumulated gd
constexpr size_t O_ggfc =O_ggd+E1;         // E1  accumulated gfcut
constexpr size_t O_ggu  =O_ggfc+E1;        // E3  accumulated gunit
constexpr size_t O_gr   =O_ggu+E3;         // E3  per-edge coord grad
constexpr size_t O_drbf =O_gr+E3;          // ENB d(rbf)/dd table
constexpr size_t O_wcat =O_drbf+ENB;       // 2 x 128*256 combined [U|V]
constexpr size_t TOTALF =O_wcat+2*128*256;

__device__ float  g_buf[TOTALF];
__device__ double g_epart[1024];
// CSR: roles [0,NAT)=dst lists, [NAT,2*NAT)=src lists
__device__ int g_cnt[2*NAT];
__device__ int g_cur[2*NAT];
__device__ int g_off[2*NAT+1];
__device__ int g_lst[2*NEg];

// ----------------------------------------------------------------------------
__global__ void zero_f_k(float* p, size_t n){
    size_t i=(size_t)blockIdx.x*blockDim.x+threadIdx.x;
    size_t stride=(size_t)gridDim.x*blockDim.x;
    for(; i<n; i+=stride) p[i]=0.f;
}
__global__ void zero_ii_k(){
    int i=blockIdx.x*blockDim.x+threadIdx.x;
    if(i<2*NAT){ g_cnt[i]=0; g_cur[i]=0; }
}
__global__ void wcat_k(const float* __restrict__ U, const float* __restrict__ V){
    int i=blockIdx.x*blockDim.x+threadIdx.x;
    if(i>=2*128*256) return;
    int b=i>>15, rem=i&32767;
    int k=rem>>8, j=rem&255;
    float v=(j<128)? U[(size_t)b*16384+k*128+j] : V[(size_t)b*16384+k*128+j-128];
    g_buf[O_wcat+i]=v;
}

// ----------------------------------------------------------------------------
__global__ void edge_geom_k(const float* __restrict__ coord, const int* __restrict__ ei){
    int e=blockIdx.x*blockDim.x+threadIdx.x;
    if(e>=NEg) return;
    int src=ei[e], dst=ei[NEg+e];
    float rx=coord[dst*3+0]-coord[src*3+0];
    float ry=coord[dst*3+1]-coord[src*3+1];
    float rz=coord[dst*3+2]-coord[src*3+2];
    float d=sqrtf(rx*rx+ry*ry+rz*rz+1e-12f);
    float inv=1.f/d;
    g_buf[O_d+e]=d;
    g_buf[O_unit+(size_t)e*3+0]=rx*inv;
    g_buf[O_unit+(size_t)e*3+1]=ry*inv;
    g_buf[O_unit+(size_t)e*3+2]=rz*inv;
    const float C=sqrtf(2.f/RC);
    #pragma unroll
    for(int k=0;k<NBs;k++){
        float a=(k+1)*PIF/RC;
        float s,c; sincosf(a*d,&s,&c);
        g_buf[O_rbf +(size_t)e*NBs+k]=C*s*inv;
        g_buf[O_drbf+(size_t)e*NBs+k]=C*(a*c - s*inv)*inv;
    }
    g_buf[O_fcut+e]=(d<RC)?0.5f*(cosf(PIF*d/RC)+1.f):0.f;
}

__global__ void embed_k(const int* __restrict__ at_no, const float* __restrict__ emb){
    size_t i=(size_t)blockIdx.x*blockDim.x+threadIdx.x;
    if(i>=NF) return;
    int n=(int)(i>>7), f=(int)(i&127);
    g_buf[O_x0+i]=emb[(size_t)at_no[n]*FD+f];
}

// ----------------------------------------------------------------------------
// fp32 GEMM: C[M,N]=act(A[M,K]@Wop+bias+Cadd). BM=BN=64, BK=16, 128 threads,
// 8x4 microtile, float4, double-buffered. M%64==0, N%64==0, K%16==0.
template<int TRANSW>
__global__ __launch_bounds__(128) void gemm2_k(
    const float* __restrict__ A, const float* __restrict__ W,
    const float* __restrict__ bias, const float* __restrict__ Cadd,
    float* __restrict__ C, float* __restrict__ Z,
    int M,int K,int N,int act)
{
    __shared__ float As[2][16][68];
    __shared__ float Ws[2][16][68];
    const int tid=threadIdx.x;
    const int tx=tid&15, ty=tid>>4;
    const int m0=blockIdx.y*64, n0=blockIdx.x*64;

    float acc[8][4];
    #pragma unroll
    for(int i=0;i<8;i++)
        #pragma unroll
        for(int j=0;j<4;j++) acc[i][j]=0.f;

    const int nt=K>>4;
    float4 pa[2], pw[2];

    #pragma unroll
    for(int i=0;i<2;i++){
        int idx=tid+i*128;
        int r=idx>>2, kq=idx&3;
        pa[i]=*(const float4*)&A[(size_t)(m0+r)*K + kq*4];
        if(TRANSW){
            pw[i]=*(const float4*)&W[(size_t)(n0+r)*K + kq*4];
        } else {
            int kk=idx>>4, nq=idx&15;
            pw[i]=*(const float4*)&W[(size_t)kk*N + n0+nq*4];
        }
    }
    #pragma unroll
    for(int i=0;i<2;i++){
        int idx=tid+i*128;
        int r=idx>>2, kq=idx&3;
        As[0][kq*4+0][r]=pa[i].x; As[0][kq*4+1][r]=pa[i].y;
        As[0][kq*4+2][r]=pa[i].z; As[0][kq*4+3][r]=pa[i].w;
        if(TRANSW){
            Ws[0][kq*4+0][r]=pw[i].x; Ws[0][kq*4+1][r]=pw[i].y;
            Ws[0][kq*4+2][r]=pw[i].z; Ws[0][kq*4+3][r]=pw[i].w;
        } else {
            int kk=idx>>4, nq=idx&15;
            *(float4*)&Ws[0][kk][nq*4]=pw[i];
        }
    }
    __syncthreads();

    for(int t=0;t<nt;t++){
        int buf=t&1;
        if(t+1<nt){
            int k0=(t+1)*16;
            #pragma unroll
            for(int i=0;i<2;i++){
                int idx=tid+i*128;
                int r=idx>>2, kq=idx&3;
                pa[i]=*(const float4*)&A[(size_t)(m0+r)*K + k0 + kq*4];
                if(TRANSW){
                    pw[i]=*(const float4*)&W[(size_t)(n0+r)*K + k0 + kq*4];
                } else {
                    int kk=idx>>4, nq=idx&15;
                    pw[i]=*(const float4*)&W[(size_t)(k0+kk)*N + n0+nq*4];
                }
            }
        }
        #pragma unroll
        for(int kk=0;kk<16;kk++){
            float4 a0=*(const float4*)&As[buf][kk][ty*8];
            float4 a1=*(const float4*)&As[buf][kk][ty*8+4];
            float4 w0=*(const float4*)&Ws[buf][kk][tx*4];
            float av[8]={a0.x,a0.y,a0.z,a0.w,a1.x,a1.y,a1.z,a1.w};
            #pragma unroll
            for(int i=0;i<8;i++){
                acc[i][0]+=av[i]*w0.x;
                acc[i][1]+=av[i]*w0.y;
                acc[i][2]+=av[i]*w0.z;
                acc[i][3]+=av[i]*w0.w;
            }
        }
        if(t+1<nt){
            int nb=buf^1;
            #pragma unroll
            for(int i=0;i<2;i++){
                int idx=tid+i*128;
                int r=idx>>2, kq=idx&3;
                As[nb][kq*4+0][r]=pa[i].x; As[nb][kq*4+1][r]=pa[i].y;
                As[nb][kq*4+2][r]=pa[i].z; As[nb][kq*4+3][r]=pa[i].w;
                if(TRANSW){
                    Ws[nb][kq*4+0][r]=pw[i].x; Ws[nb][kq*4+1][r]=pw[i].y;
                    Ws[nb][kq*4+2][r]=pw[i].z; Ws[nb][kq*4+3][r]=pw[i].w;
                } else {
                    int kk=idx>>4, nq=idx&15;
                    *(float4*)&Ws[nb][kk][nq*4]=pw[i];
                }
            }
            __syncthreads();
        }
    }

    const int n=n0+tx*4;
    float4 bb={0.f,0.f,0.f,0.f};
    if(bias) bb=*(const float4*)&bias[n];
    #pragma unroll
    for(int i=0;i<8;i++){
        int m=m0+ty*8+i;
        float4 v={acc[i][0]+bb.x,acc[i][1]+bb.y,acc[i][2]+bb.z,acc[i][3]+bb.w};
        size_t off=(size_t)m*N+n;
        if(Cadd){
            float4 cc=*(const float4*)&Cadd[off];
            v.x+=cc.x; v.y+=cc.y; v.z+=cc.z; v.w+=cc.w;
        }
        if(act==1){
            if(Z) *(float4*)&Z[off]=v;
            v.x=siluf(v.x); v.y=siluf(v.y); v.z=siluf(v.z); v.w=siluf(v.w);
        } else if(act==2){
            float4 zz=*(const float4*)&Z[off];
            v.x*=silugf(zz.x); v.y*=silugf(zz.y); v.z*=silugf(zz.z); v.w*=silugf(zz.w);
        }
        *(float4*)&C[off]=v;
    }
}

static inline void gemm2(const float*A,const float*W,const float*b,const float*Cadd,
                         float*C,float*Z,int M,int K,int N,int act,int transW){
    dim3 g(N/64, M/64);
    if(transW) gemm2_k<1><<<g,128>>>(A,W,b,Cadd,C,Z,M,K,N,act);
    else       gemm2_k<0><<<g,128>>>(A,W,b,Cadd,C,Z,M,K,N,act);
}

// ----------------------------------------------------------------------------
// CSR build
__global__ void count_k(const int* __restrict__ ei){
    int e=blockIdx.x*blockDim.x+threadIdx.x;
    if(e>=NEg) return;
    atomicAdd(&g_cnt[ei[NEg+e]],1);
    atomicAdd(&g_cnt[NAT+ei[e]],1);
}
__global__ __launch_bounds__(1024) void scan_k(){
    __shared__ int part[1024];
    int t=threadIdx.x;
    int loc[16]; int s=0;
    #pragma unroll
    for(int i=0;i<16;i++){ loc[i]=s; s+=g_cnt[t*16+i]; }
    part[t]=s;
    __syncthreads();
    if(t==0){
        int acc=0;
        for(int i=0;i<1024;i++){ int v=part[i]; part[i]=acc; acc+=v; }
        g_off[2*NAT]=acc;
    }
    __syncthreads();
    int b=part[t];
    #pragma unroll
    for(int i=0;i<16;i++) g_off[t*16+i]=b+loc[i];
}
__global__ void fill_k(const int* __restrict__ ei){
    int e=blockIdx.x*blockDim.x+threadIdx.x;
    if(e>=NEg) return;
    int d=ei[NEg+e], s=ei[e];
    int p=atomicAdd(&g_cur[d],1);      g_lst[g_off[d]+p]=e;
    int q=atomicAdd(&g_cur[NAT+s],1);  g_lst[g_off[NAT+s]+q]=e;
}
__global__ void sort_k(){
    int l=blockIdx.x*blockDim.x+threadIdx.x;
    if(l>=2*NAT) return;
    int s=g_off[l], en=g_off[l+1];
    for(int i=s+1;i<en;i++){
        int v=g_lst[i]; int j=i-1;
        while(j>=s && g_lst[j]>v){ g_lst[j+1]=g_lst[j]; j--; }
        g_lst[j+1]=v;
    }
}

// ----------------------------------------------------------------------------
// message forward: one block per DST atom, register accumulation, no atomics
__global__ __launch_bounds__(128) void msg_fwd_csr_k(
    const int* __restrict__ ei, const float* __restrict__ Wr, const float* __restrict__ br,
    const float* __restrict__ phi, const float* __restrict__ x_in,
    const float* __restrict__ v_in,
    float* __restrict__ xmid, float* __restrict__ vmid)
{
    __shared__ float wS[NBs*F3];
    __shared__ float brS[F3];
    int t=threadIdx.x;
    for(int i=t;i<NBs*F3/4;i+=128) ((float4*)wS)[i]=((const float4*)Wr)[i];
    if(t<F3/4) ((float4*)brS)[t]=((const float4*)br)[t];
    __syncthreads();
    int n=blockIdx.x;
    int c0=t,c1=FD+t,c2=2*FD+t;
    float b0=brS[c0],b1=brS[c1],b2=brS[c2];
    float ax =x_in[(size_t)n*FD+t];
    float av0=v_in[((size_t)n*3+0)*FD+t];
    float av1=v_in[((size_t)n*3+1)*FD+t];
    float av2=v_in[((size_t)n*3+2)*FD+t];
    int s0=g_off[n], s1=g_off[n+1];
    for(int j=s0;j<s1;j++){
        int e=g_lst[j];
        int src=ei[e];
        float fc=g_buf[O_fcut+e];
        float u0=g_buf[O_unit+(size_t)e*3+0];
        float u1=g_buf[O_unit+(size_t)e*3+1];
        float u2=g_buf[O_unit+(size_t)e*3+2];
        const float* rb=&g_buf[O_rbf+(size_t)e*NBs];
        float g0=b0,g1=b1,g2=b2;
        #pragma unroll
        for(int k=0;k<NBs;k++){
            float r=rb[k];
            g0+=r*wS[k*F3+c0]; g1+=r*wS[k*F3+c1]; g2+=r*wS[k*F3+c2];
        }
        float f0=g0*fc, f1=g1*fc, f2=g2*fc;
        const float* ps=phi+(size_t)src*F3;
        ax += ps[c0]*f0;
        float m1=ps[c1]*f1, m2=ps[c2]*f2;
        av0 += m1*v_in[((size_t)src*3+0)*FD+t]+m2*u0;
        av1 += m1*v_in[((size_t)src*3+1)*FD+t]+m2*u1;
        av2 += m1*v_in[((size_t)src*3+2)*FD+t]+m2*u2;
    }
    xmid[(size_t)n*FD+t]=ax;
    vmid[((size_t)n*3+0)*FD+t]=av0;
    vmid[((size_t)n*3+1)*FD+t]=av1;
    vmid[((size_t)n*3+2)*FD+t]=av2;
}

// message backward: one block per SRC atom, register accumulation
__global__ __launch_bounds__(128) void msg_bwd_csr_k(
    const int* __restrict__ ei, const float* __restrict__ Wr, const float* __restrict__ br,
    const float* __restrict__ phi, const float* __restrict__ v_in,
    const float* __restrict__ gx_mid, const float* __restrict__ gv_mid,
    float* __restrict__ gv_prev, float* __restrict__ gphi)
{
    __shared__ float wS[NBs*F3];
    __shared__ float brS[F3];
    __shared__ float accS[8];
    int t=threadIdx.x;
    for(int i=t;i<NBs*F3/4;i+=128) ((float4*)wS)[i]=((const float4*)Wr)[i];
    if(t<F3/4) ((float4*)brS)[t]=((const float4*)br)[t];
    __syncthreads();
    int m=blockIdx.x;
    int c0=t,c1=FD+t,c2=2*FD+t;
    int lane=t&31;
    float b0=brS[c0],b1=brS[c1],b2=brS[c2];
    float p0=phi[(size_t)m*F3+c0];
    float p1=phi[(size_t)m*F3+c1];
    float p2=phi[(size_t)m*F3+c2];
    float vs0=v_in[((size_t)m*3+0)*FD+t];
    float vs1=v_in[((size_t)m*3+1)*FD+t];
    float vs2=v_in[((size_t)m*3+2)*FD+t];
    float agv0=gv_mid[((size_t)m*3+0)*FD+t];
    float agv1=gv_mid[((size_t)m*3+1)*FD+t];
    float agv2=gv_mid[((size_t)m*3+2)*FD+t];
    float aph0=0.f, aph1=0.f, aph2=0.f;
    int s0=g_off[NAT+m], s1=g_off[NAT+m+1];
    for(int j=s0;j<s1;j++){
        int e=g_lst[j];
        if(t<5) accS[t]=0.f;
        int dst=ei[NEg+e];
        float fc=g_buf[O_fcut+e];
        float u0=g_buf[O_unit+(size_t)e*3+0];
        float u1=g_buf[O_unit+(size_t)e*3+1];
        float u2=g_buf[O_unit+(size_t)e*3+2];
        const float* rb=&g_buf[O_rbf +(size_t)e*NBs];
        const float* db=&g_buf[O_drbf+(size_t)e*NBs];
        float g0=b0,g1=b1,g2=b2;
        float wd0=0.f,wd1=0.f,wd2=0.f;
        #pragma unroll
        for(int k=0;k<NBs;k++){
            float w0=wS[k*F3+c0], w1=wS[k*F3+c1], w2=wS[k*F3+c2];
            float r=rb[k], dr=db[k];
            g0+=r*w0; g1+=r*w1; g2+=r*w2;
            wd0+=dr*w0; wd1+=dr*w1; wd2+=dr*w2;
        }
        float f0=g0*fc,f1=g1*fc,f2=g2*fc;
        float gds=gx_mid[(size_t)dst*FD+t];
        float gd0=gv_mid[((size_t)dst*3+0)*FD+t];
        float gd1=gv_mid[((size_t)dst*3+1)*FD+t];
        float gd2=gv_mid[((size_t)dst*3+2)*FD+t];
        float gm1=gd0*vs0+gd1*vs1+gd2*vs2;
        float gm2=gd0*u0+gd1*u1+gd2*u2;
        float m1=p1*f1, m2=p2*f2;
        agv0+=m1*gd0; agv1+=m1*gd1; agv2+=m1*gd2;
        aph0+=gds*f0; aph1+=gm1*f1; aph2+=gm2*f2;
        float gf0=gds*p0, gf1=gm1*p1, gf2=gm2*p2;
        float gg0=gf0*fc, gg1=gf1*fc, gg2=gf2*fc;
        float vals[5];
        vals[0]=gg0*wd0+gg1*wd1+gg2*wd2;
        vals[1]=gf0*g0+gf1*g1+gf2*g2;
        vals[2]=gd0*m2; vals[3]=gd1*m2; vals[4]=gd2*m2;
        __syncthreads();
        #pragma unroll
        for(int q=0;q<5;q++){
            float v=vals[q];
            #pragma unroll
            for(int o=16;o;o>>=1) v+=__shfl_down_sync(0xffffffffu,v,o);
            if(lane==0) atomicAdd(&accS[q],v);
        }
        __syncthreads();
        if(t==0)      g_buf[O_ggd +e]+=accS[0];
        else if(t==1) g_buf[O_ggfc+e]+=accS[1];
        else if(t<5)  g_buf[O_ggu+(size_t)e*3+(t-2)]+=accS[t];
    }
    gv_prev[((size_t)m*3+0)*FD+t]=agv0;
    gv_prev[((size_t)m*3+1)*FD+t]=agv1;
    gv_prev[((size_t)m*3+2)*FD+t]=agv2;
    gphi[(size_t)m*F3+c0]=aph0;
    gphi[(size_t)m*F3+c1]=aph1;
    gphi[(size_t)m*F3+c2]=aph2;
}

// ----------------------------------------------------------------------------
// uvv layout: [3*NAT, 256], cols 0-127 = uv, 128-255 = vv
__global__ void vnorm_cat_k(const float* __restrict__ uvv, const float* __restrict__ xmid,
                            float* __restrict__ vn, float* __restrict__ cat){
    size_t i=(size_t)blockIdx.x*blockDim.x+threadIdx.x;
    if(i>=NF) return;
    int n=(int)(i>>7), f=(int)(i&127);
    float a=uvv[((size_t)n*3+0)*256+128+f];
    float b=uvv[((size_t)n*3+1)*256+128+f];
    float c=uvv[((size_t)n*3+2)*256+128+f];
    float v=sqrtf(a*a+b*b+c*c+1e-12f);
    vn[i]=v;
    cat[(size_t)n*2*FD+f]=xmid[i];
    cat[(size_t)n*2*FD+FD+f]=v;
}

__global__ void upd_fwd_k(const float* __restrict__ a, const float* __restrict__ uvv,
                          const float* __restrict__ vmid, const float* __restrict__ xmid,
                          float* __restrict__ xout, float* __restrict__ vout){
    size_t i=(size_t)blockIdx.x*blockDim.x+threadIdx.x;
    if(i>=NF) return;
    int n=(int)(i>>7), f=(int)(i&127);
    const float* an=a+(size_t)n*F3;
    float avv=an[f], asv=an[FD+f], ass=an[2*FD+f];
    float sdot=0.f;
    #pragma unroll
    for(int k=0;k<3;k++){
        size_t r2=((size_t)n*3+k)*256+f;
        float u=uvv[r2], w=uvv[r2+128];
        sdot+=u*w;
        vout[((size_t)n*3+k)*FD+f]=vmid[((size_t)n*3+k)*FD+f]+avv*u;
    }
    xout[i]=xmid[i]+asv*sdot+ass;
}

__global__ void energy_k(const float* __restrict__ s3, const float* __restrict__ ow2,
                         const float* __restrict__ ob2, const float* __restrict__ atom_sp,
                         const int* __restrict__ at_no){
    __shared__ double wsum[8];
    int warp=threadIdx.x>>5, lane=threadIdx.x&31;
    int n=blockIdx.x*8+warp;
    float val=s3[(size_t)n*NHd+lane]*ow2[lane]+s3[(size_t)n*NHd+32+lane]*ow2[32+lane];
    #pragma unroll
    for(int o=16;o;o>>=1) val+=__shfl_down_sync(0xffffffffu,val,o);
    if(lane==0) wsum[warp]=(double)val+(double)ob2[0]+(double)atom_sp[at_no[n]];
    __syncthreads();
    if(threadIdx.x==0){
        double s=0.0;
        #pragma unroll
        for(int i=0;i<8;i++) s+=wsum[i];
        g_epart[blockIdx.x]=s;
    }
}
__global__ void store_e_k(float* out){
    __shared__ double sh[256];
    int t=threadIdx.x;
    sh[t]=g_epart[t]+g_epart[t+256]+g_epart[t+512]+g_epart[t+768];
    __syncthreads();
    for(int o=128;o;o>>=1){ if(t<o) sh[t]+=sh[t+o]; __syncthreads(); }
    if(t==0) out[0]=(float)sh[0];
}

__global__ void gz3_k(const float* __restrict__ z3, const float* __restrict__ ow2,
                      float* __restrict__ gz3){
    size_t i=(size_t)blockIdx.x*blockDim.x+threadIdx.x;
    if(i>=NHs) return;
    int h=(int)(i&(NHd-1));
    gz3[i]=ow2[h]*silugf(z3[i]);
}

// update backward part 1: reads uvv, writes ga + guvv (interleaved [.,256])
__global__ void upd_bwd1_k(const float* __restrict__ gx_in, const float* __restrict__ gv_in,
                           const float* __restrict__ uvv, const float* __restrict__ a,
                           float* __restrict__ ga, float* __restrict__ guvv){
    size_t i=(size_t)blockIdx.x*blockDim.x+threadIdx.x;
    if(i>=NF) return;
    int n=(int)(i>>7), f=(int)(i&127);
    const float* an=a+(size_t)n*F3;
    float avv=an[f], asv=an[FD+f];
    float gx=gx_in[i];
    float sdot=0.f, gavv=0.f;
    float uvr[3],vvr[3],gvr[3];
    #pragma unroll
    for(int k=0;k<3;k++){
        size_t r2=((size_t)n*3+k)*256+f;
        uvr[k]=uvv[r2]; vvr[k]=uvv[r2+128];
        gvr[k]=gv_in[((size_t)n*3+k)*FD+f];
        sdot+=uvr[k]*vvr[k];
        gavv+=gvr[k]*uvr[k];
    }
    float gsdot=gx*asv;
    float* gan=ga+(size_t)n*F3;
    gan[f]=gavv; gan[FD+f]=gx*sdot; gan[2*FD+f]=gx;
    #pragma unroll
    for(int k=0;k<3;k++){
        size_t r2=((size_t)n*3+k)*256+f;
        guvv[r2]=gvr[k]*avv+gsdot*vvr[k];
        guvv[r2+128]=gsdot*uvr[k];
    }
}

// update backward part 3: gvv part of guvv += (gvn/vn)*vv
__global__ void upd_bwd3_k(const float* __restrict__ gcat, const float* __restrict__ gx_in,
                           const float* __restrict__ uvv, const float* __restrict__ vn,
                           float* __restrict__ gx_mid, float* __restrict__ guvv){
    size_t i=(size_t)blockIdx.x*blockDim.x+threadIdx.x;
    if(i>=NF) return;
    int n=(int)(i>>7), f=(int)(i&127);
    gx_mid[i]=gx_in[i]+gcat[(size_t)n*2*FD+f];
    float gvn=gcat[(size_t)n*2*FD+FD+f];
    float inv=gvn/vn[i];
    #pragma unroll
    for(int k=0;k<3;k++){
        size_t r2=((size_t)n*3+k)*256+f;
        guvv[r2+128]+=inv*uvv[r2+128];
    }
}

// final per-edge coord gradient
__global__ void edge_gr_k(){
    int e=blockIdx.x*blockDim.x+threadIdx.x;
    if(e>=NEg) return;
    float d=g_buf[O_d+e];
    float inv=1.f/d;
    float u0=g_buf[O_unit+(size_t)e*3+0];
    float u1=g_buf[O_unit+(size_t)e*3+1];
    float u2=g_buf[O_unit+(size_t)e*3+2];
    float gd=g_buf[O_ggd+e];
    if(d<RC) gd+=g_buf[O_ggfc+e]*(-0.5f*PIF/RC*sinf(PIF*d/RC));
    float gu0=g_buf[O_ggu+(size_t)e*3+0];
    float gu1=g_buf[O_ggu+(size_t)e*3+1];
    float gu2=g_buf[O_ggu+(size_t)e*3+2];
    float dot=gu0*u0+gu1*u1+gu2*u2;
    g_buf[O_gr+(size_t)e*3+0]=gd*u0+(gu0-dot*u0)*inv;
    g_buf[O_gr+(size_t)e*3+1]=gd*u1+(gu1-dot*u1)*inv;
    g_buf[O_gr+(size_t)e*3+2]=gd*u2+(gu2-dot*u2)*inv;
}

// deterministic reference-order scatter
__global__ void out_k(float* __restrict__ gout){
    int i=blockIdx.x*blockDim.x+threadIdx.x;
    if(i>=NAT*3) return;
    int n=i/3, c=i%3;
    float A=0.f;
    int s0=g_off[n], e0=g_off[n+1];
    for(int j=s0;j<e0;j++){ int e=g_lst[j]; A+=g_buf[O_gr+(size_t)e*3+c]; }
    float Bv=0.f;
    int s1=g_off[NAT+n], e1=g_off[NAT+n+1];
    for(int j=s1;j<e1;j++){ int e=g_lst[j]; Bv-=g_buf[O_gr+(size_t)e*3+c]; }
    gout[i]=A+Bv;
}

// ----------------------------------------------------------------------------
extern "C" void kernel_launch(void* const* d_in, const int* in_sizes, int n_in,
                              void* d_out, int out_size){
    float* B=nullptr;
    cudaGetSymbolAddress((void**)&B, g_buf);

    const int*   at_no=(const int*)d_in[0];
    const float* coord=(const float*)d_in[1];
    const int*   ei   =(const int*)d_in[2];
    int p=(in_sizes[3]==1)?5:3;
    const float* emb    =(const float*)d_in[p+0];
    const float* atom_sp=(const float*)d_in[p+1];
    const float* msg_w1 =(const float*)d_in[p+2];
    const float* msg_b1 =(const float*)d_in[p+3];
    const float* msg_w2 =(const float*)d_in[p+4];
    const float* msg_b2 =(const float*)d_in[p+5];
    const float* msg_wr =(const float*)d_in[p+6];
    const float* msg_br =(const float*)d_in[p+7];
    const float* upd_u  =(const float*)d_in[p+8];
    const float* upd_v  =(const float*)d_in[p+9];
    const float* upd_w1 =(const float*)d_in[p+10];
    const float* upd_b1 =(const float*)d_in[p+11];
    const float* upd_w2 =(const float*)d_in[p+12];
    const float* upd_b2 =(const float*)d_in[p+13];
    const float* out_w1 =(const float*)d_in[p+14];
    const float* out_b1 =(const float*)d_in[p+15];
    const float* out_w2 =(const float*)d_in[p+16];
    const float* out_b2 =(const float*)d_in[p+17];
    float* out=(float*)d_out;

    const size_t xs[3]={O_x0,O_x1,O_x2};
    const size_t vs[3]={O_v0,O_v1,O_v2};

    // prologue (first GEMM early for ncu window)
    edge_geom_k<<<(NEg+255)/256,256>>>(coord,ei);             // 0
    embed_k<<<(int)((NF+255)/256),256>>>(at_no,emb);          // 1
    zero_f_k<<<4096,256>>>(B+O_v0,N3F);                       // 2
    gemm2(B+O_x0, msg_w1, msg_b1, nullptr, B+O_cat,
          B+O_z1, NAT,FD,FD,1,0);                             // 3 <- target profile
    gemm2(B+O_cat, msg_w2, msg_b2, nullptr, B+O_phi,
          nullptr, NAT,FD,F3,0,0);                            // 4
    zero_ii_k<<<64,256>>>();
    wcat_k<<<(2*128*256+255)/256,256>>>(upd_u, upd_v);
    count_k<<<(NEg+255)/256,256>>>(ei);
    scan_k<<<1,1024>>>();
    fill_k<<<(NEg+255)/256,256>>>(ei);
    sort_k<<<(2*NAT+255)/256,256>>>();

    // ---- forward ----
    for(int b=0;b<2;b++){
        float* x_in=B+xs[b];  float* v_in=B+vs[b];
        float* xmid=B+(b?O_xm1:O_xm0);
        float* vmid=B+(b?O_vm1:O_vm0);
        float* uvv =B+O_uv+(size_t)b*2*N3F;
        if(b==1){
            gemm2(x_in, msg_w1+(size_t)b*FD*FD, msg_b1+(size_t)b*FD,
                  nullptr, B+O_cat, B+O_z1+(size_t)b*NF, NAT,FD,FD,1,0);
            gemm2(B+O_cat, msg_w2+(size_t)b*FD*F3, msg_b2+(size_t)b*F3,
                  nullptr, B+O_phi+(size_t)b*NF3, nullptr, NAT,FD,F3,0,0);
        }
        msg_fwd_csr_k<<<NAT,128>>>(ei, msg_wr+(size_t)b*NBs*F3, msg_br+(size_t)b*F3,
                                   B+O_phi+(size_t)b*NF3, x_in, v_in, xmid, vmid);
        // uvv = vmid @ [U|V]
        gemm2(vmid, B+O_wcat+(size_t)b*32768, nullptr,nullptr,
              uvv, nullptr, 3*NAT,FD,256,0,0);
        vnorm_cat_k<<<(int)((NF+255)/256),256>>>(uvv, xmid,
                                                 B+O_vn+(size_t)b*NF, B+O_cat);
        gemm2(B+O_cat, upd_w1+(size_t)b*2*FD*FD, upd_b1+(size_t)b*FD,
              nullptr, B+O_gs, B+O_z2+(size_t)b*NF, NAT,2*FD,FD,1,0);
        gemm2(B+O_gs, upd_w2+(size_t)b*FD*F3, upd_b2+(size_t)b*F3,
              nullptr, B+O_a+(size_t)b*NF3, nullptr, NAT,FD,F3,0,0);
        upd_fwd_k<<<(int)((NF+255)/256),256>>>(B+O_a+(size_t)b*NF3, uvv,
                                               vmid, xmid, B+xs[b+1], B+vs[b+1]);
    }

    // ---- readout + energy ----
    gemm2(B+O_x2, out_w1, out_b1, nullptr, B+O_s3, B+O_z3, NAT,FD,NHd,1,0);
    energy_k<<<NAT/8,256>>>(B+O_s3, out_w2, out_b2, atom_sp, at_no);

    // ---- zero geometry-grad accumulators ----
    zero_f_k<<<1024,256>>>(B+O_ggd, 5*E1);

    // ---- backward readout ----
    gz3_k<<<(int)((NHs+255)/256),256>>>(B+O_z3, out_w2, B+O_s3);
    gemm2(B+O_s3, out_w1, nullptr, nullptr, B+O_gxA, nullptr, NAT,NHd,FD,0,1);
    float* gvbuf[3]={B+O_gv0,B+O_gv1,B+O_gv2};
    int ib=0;
    zero_f_k<<<4096,256>>>(gvbuf[0],N3F);

    // ---- backward blocks ----
    for(int b=1;b>=0;b--){
        float* gv_in  =gvbuf[ib];
        float* gv_mid =gvbuf[(ib+1)%3];
        float* gv_prev=gvbuf[(ib+2)%3];
        float* gx_in=B+O_gxA;
        float* gx_mid=B+O_gxB;
        float* v_in=B+vs[b];
        float* uvv =B+O_uv+(size_t)b*2*N3F;

        upd_bwd1_k<<<(int)((NF+255)/256),256>>>(gx_in, gv_in,
                uvv, B+O_a+(size_t)b*NF3, B+O_ga, B+O_guv);
        gemm2(B+O_ga, upd_w2+(size_t)b*FD*F3, nullptr, nullptr,
              B+O_gs, B+O_z2+(size_t)b*NF, NAT,F3,FD,2,1);
        gemm2(B+O_gs, upd_w1+(size_t)b*2*FD*FD, nullptr, nullptr,
              B+O_gcat, nullptr, NAT,FD,2*FD,0,1);
        upd_bwd3_k<<<(int)((NF+255)/256),256>>>(B+O_gcat, gx_in,
                uvv, B+O_vn+(size_t)b*NF, gx_mid, B+O_guv);
        // gv_mid = [guv|gvv] @ [U;V]^T + gv_in   (single K=256 GEMM)
        gemm2(B+O_guv, B+O_wcat+(size_t)b*32768, nullptr, gv_in,
              gv_mid, nullptr, 3*NAT,256,FD,0,1);
        msg_bwd_csr_k<<<NAT,128>>>(ei, msg_wr+(size_t)b*NBs*F3, msg_br+(size_t)b*F3,
                                   B+O_phi+(size_t)b*NF3, v_in, gx_mid, gv_mid,
                                   gv_prev, B+O_gphi);
        if(b>0){
            gemm2(B+O_gphi, msg_w2+(size_t)b*FD*F3, nullptr, nullptr,
                  B+O_gs, B+O_z1+(size_t)b*NF, NAT,F3,FD,2,1);
            gemm2(B+O_gs, msg_w1+(size_t)b*FD*FD, nullptr, gx_mid,
                  B+O_gxA, nullptr, NAT,FD,FD,0,1);
        }
        ib=(ib+2)%3;
    }

    // ---- geometry grads -> coord grads ----
    edge_gr_k<<<(NEg+255)/256,256>>>();
    out_k<<<(3*NAT+255)/256,256>>>(out+1);
    store_e_k<<<1,256>>>(out);
}